// round 2
// baseline (speedup 1.0000x reference)
#include <cuda_runtime.h>
#include <cstdint>

// Problem constants
#define B_   4
#define N_   24
#define C_   256
#define H_   100
#define W_   100
#define OUT_ 7
#define P_   276                    // N*(N-1)/2
#define CH_  (C_ * OUT_ * OUT_)     // 12544 floats per [C,7,7] chunk
#define CH_BYTES_ (CH_ * 4)         // 50176 bytes (multiple of 16)
#define HW_  (H_ * W_)
#define SCALE_ 0.25f

// NHWC scratch for features
__device__ float g_nhwc[(size_t)B_ * HW_ * C_];

// ---------------------------------------------------------------------------
// PTX helpers: 1D bulk async copy SMEM -> GMEM (TMA store path)
// ---------------------------------------------------------------------------
__device__ __forceinline__ uint32_t smem_u32(const void* p) {
    uint32_t a;
    asm("{ .reg .u64 t; cvta.to.shared.u64 t, %1; cvt.u32.u64 %0, t; }"
        : "=r"(a) : "l"(p));
    return a;
}
__device__ __forceinline__ void bulk_s2g(void* gmem, uint32_t smem, uint32_t bytes) {
    asm volatile("cp.async.bulk.global.shared::cta.bulk_group [%0], [%1], %2;"
                 :: "l"(gmem), "r"(smem), "r"(bytes) : "memory");
}
__device__ __forceinline__ void bulk_commit() {
    asm volatile("cp.async.bulk.commit_group;" ::: "memory");
}
__device__ __forceinline__ void bulk_wait_read0() {
    asm volatile("cp.async.bulk.wait_group.read 0;" ::: "memory");
}
__device__ __forceinline__ void fence_proxy_async_shared() {
    asm volatile("fence.proxy.async.shared::cta;" ::: "memory");
}

// ---------------------------------------------------------------------------
// Kernel 1: NCHW -> NHWC transpose, float4 stores.
// ---------------------------------------------------------------------------
__global__ void nchw_to_nhwc_kernel(const float* __restrict__ in) {
    __shared__ float tile[32][33];
    const int b   = blockIdx.z;
    const int c0  = blockIdx.y * 32;
    const int hw0 = blockIdx.x * 32;
    const int tx = threadIdx.x, ty = threadIdx.y;   // (32, 8)
    const int tid = ty * 32 + tx;

    const float* src = in + (size_t)b * C_ * HW_;
#pragma unroll
    for (int i = 0; i < 32; i += 8) {
        const int c  = c0 + ty + i;
        const int hw = hw0 + tx;
        float v = 0.0f;
        if (hw < HW_) v = src[(size_t)c * HW_ + hw];
        tile[ty + i][tx] = v;
    }
    __syncthreads();

    // Store side: tid -> (tx8 in [0,8) = float4 channel group, tyy in [0,32) = hw)
    const int tx8 = tid & 7;
    const int tyy = tid >> 3;
    const int hw  = hw0 + tyy;
    if (hw < HW_) {
        float4 v;
        v.x = tile[4 * tx8 + 0][tyy];
        v.y = tile[4 * tx8 + 1][tyy];
        v.z = tile[4 * tx8 + 2][tyy];
        v.w = tile[4 * tx8 + 3][tyy];
        float* dst = g_nhwc + (size_t)b * HW_ * C_;
        *reinterpret_cast<float4*>(&dst[(size_t)hw * C_ + c0 + 4 * tx8]) = v;
    }
}

// ---------------------------------------------------------------------------
// Kernel 2: one CTA per roi.
//  Phase B: pooled [C,7,7] into SMEM. Octet-skewed bin assignment keeps the
//           LDG.128 wavefront count unchanged (each 8-lane octet contiguous)
//           while making the stride-196 STS pattern fully bank-conflict-free.
//  Phase C: cp.async.bulk SMEM->GMEM, one bulk op per destination tile.
// ---------------------------------------------------------------------------
__global__ __launch_bounds__(256) void roi_pair_kernel(
    const float* __restrict__ boxes,   // [B, N, 4] xyxy, image coords
    float* __restrict__ out)           // [B*P, 3, C, 7, 7]
{
    __shared__ __align__(16) float pooled[CH_];
    __shared__ int   sy0[14], sy1[14], sx0[14], sx1[14];
    __shared__ float sly[14], shy[14], slx[14], shx[14];
    __shared__ float roi[4];

    const int bid = blockIdx.x;
    const int tid = threadIdx.x;

    int b, m;  // batch, roi index (m < N_: object, else union pair m-N_)
    if (bid < B_ * N_) { b = bid / N_; m = bid % N_; }
    else { const int u = bid - B_ * N_; b = u / P_; m = N_ + (u % P_); }

    if (tid == 0) {
        float x1, y1, x2, y2;
        if (m < N_) {
            const float* bx = boxes + ((size_t)b * N_ + m) * 4;
            x1 = bx[0]; y1 = bx[1]; x2 = bx[2]; y2 = bx[3];
        } else {
            int p = m - N_;
            int i = 0, rem = p, cnt = N_ - 1;
            while (rem >= cnt) { rem -= cnt; ++i; --cnt; }
            const int j = i + 1 + rem;
            const float* ba = boxes + ((size_t)b * N_ + i) * 4;
            const float* bb = boxes + ((size_t)b * N_ + j) * 4;
            x1 = fminf(ba[0], bb[0]);
            y1 = fminf(ba[1], bb[1]);
            x2 = fmaxf(ba[2], bb[2]);
            y2 = fmaxf(ba[3], bb[3]);
        }
        roi[0] = x1; roi[1] = y1; roi[2] = x2; roi[3] = y2;
    }
    __syncthreads();

    // Separable sample tables: tid 0..13 -> x, 14..27 -> y.
    if (tid < 28) {
        const int  d   = tid % 14;
        const bool isY = (tid >= 14);
        const float c1 = (isY ? roi[1] : roi[0]) * SCALE_;
        const float c2 = (isY ? roi[3] : roi[2]) * SCALE_;
        const float sz  = fmaxf(c2 - c1, 1.0f);
        const float bsz = sz * (1.0f / OUT_);
        const float g = (float)(d >> 1) + ((float)(d & 1) + 0.5f) * 0.5f;
        const float X = c1 + g * bsz;
        const int   lim = isY ? H_ : W_;
        const bool  valid = (X > -1.0f) && (X < (float)lim);
        const float Xc  = fminf(fmaxf(X, 0.0f), (float)(lim - 1));
        const float x0f = floorf(Xc);
        float lx = Xc - x0f;
        float hx = 1.0f - lx;
        if (!valid) { lx = 0.0f; hx = 0.0f; }
        const int x0  = (int)x0f;
        const int x1i = min(x0 + 1, lim - 1);
        if (isY) { sy0[d] = x0; sy1[d] = x1i; sly[d] = lx; shy[d] = hx; }
        else     { sx0[d] = x0; sx1[d] = x1i; slx[d] = lx; shx[d] = hx; }
    }
    __syncthreads();

    // Phase B: pooled compute with octet bin-skew.
    const int c4   = tid & 63;          // float4 channel group
    const int slot = tid >> 6;          // 0..3
    const int oct  = (tid >> 3) & 3;    // lane octet within warp
    const int boff = (slot + oct) & 3;  // bin offset, distinct mod 4 per octet
    const float4* __restrict__ feat =
        reinterpret_cast<const float4*>(g_nhwc) + (size_t)b * HW_ * (C_ / 4);

#pragma unroll 1
    for (int t = 0; t < 13; ++t) {
        const int bin = 4 * t + boff;
        if (bin >= OUT_ * OUT_) break;
        const int py = bin / OUT_;
        const int px = bin - py * OUT_;
        float4 acc = make_float4(0.f, 0.f, 0.f, 0.f);
#pragma unroll
        for (int sy = 0; sy < 2; ++sy) {
            const int   yi = 2 * py + sy;
            const int   y0 = sy0[yi], y1 = sy1[yi];
            const float ly = sly[yi], hy = shy[yi];
            const int r0 = y0 * W_;
            const int r1 = y1 * W_;
#pragma unroll
            for (int sx = 0; sx < 2; ++sx) {
                const int   xi = 2 * px + sx;
                const int   x0 = sx0[xi], x1 = sx1[xi];
                const float lx = slx[xi], hx = shx[xi];
                const float4 f00 = feat[(size_t)(r0 + x0) * 64 + c4];
                const float4 f01 = feat[(size_t)(r0 + x1) * 64 + c4];
                const float4 f10 = feat[(size_t)(r1 + x0) * 64 + c4];
                const float4 f11 = feat[(size_t)(r1 + x1) * 64 + c4];
                const float w00 = hy * hx, w01 = hy * lx, w10 = ly * hx, w11 = ly * lx;
                acc.x += w00 * f00.x + w01 * f01.x + w10 * f10.x + w11 * f11.x;
                acc.y += w00 * f00.y + w01 * f01.y + w10 * f10.y + w11 * f11.y;
                acc.z += w00 * f00.z + w01 * f01.z + w10 * f10.z + w11 * f11.z;
                acc.w += w00 * f00.w + w01 * f01.w + w10 * f10.w + w11 * f11.w;
            }
        }
        const int base = (4 * c4) * 49 + bin;   // conflict-free across the warp
        pooled[base]       = acc.x * 0.25f;
        pooled[base + 49]  = acc.y * 0.25f;
        pooled[base + 98]  = acc.z * 0.25f;
        pooled[base + 147] = acc.w * 0.25f;
    }
    __syncthreads();

    // Phase C: bulk async SMEM -> GMEM fan-out (TMA engine does the copies).
    const uint32_t psrc = smem_u32(pooled);
    bool issued = false;
    if (m < N_) {
        // 23 destinations: t < (N-1-m): slot0 pair (m, m+1+t); else slot1 pair (i, m)
        if (tid < N_ - 1) {
            fence_proxy_async_shared();
            int p, slot_o;
            const int hi = N_ - 1 - m;
            if (tid < hi) {
                const int j = m + 1 + tid;
                p = m * (N_ - 1) - (m * (m - 1)) / 2 + (j - m - 1);
                slot_o = 0;
            } else {
                const int i = tid - hi;
                p = i * (N_ - 1) - (i * (i - 1)) / 2 + (m - i - 1);
                slot_o = 1;
            }
            float* dst = out + (((size_t)b * P_ + p) * 3 + slot_o) * CH_;
            bulk_s2g(dst, psrc, CH_BYTES_);
            issued = true;
        }
    } else {
        if (tid == 0) {
            fence_proxy_async_shared();
            const int p = m - N_;
            float* dst = out + (((size_t)b * P_ + p) * 3 + 2) * CH_;
            bulk_s2g(dst, psrc, CH_BYTES_);
            issued = true;
        }
    }
    if (issued) {
        bulk_commit();
        bulk_wait_read0();   // smem safe to release at CTA exit
    }
}

// ---------------------------------------------------------------------------
extern "C" void kernel_launch(void* const* d_in, const int* in_sizes, int n_in,
                              void* d_out, int out_size) {
    const float* features = (const float*)d_in[0];  // [B,C,H,W] float32
    const float* boxes    = (const float*)d_in[1];  // [B,N,4]   float32
    float* out = (float*)d_out;

    dim3 tgrid((HW_ + 31) / 32, C_ / 32, B_);
    nchw_to_nhwc_kernel<<<tgrid, dim3(32, 8)>>>(features);

    const int nblocks = B_ * N_ + B_ * P_;
    roi_pair_kernel<<<nblocks, 256>>>(boxes, out);
}